// round 1
// baseline (speedup 1.0000x reference)
#include <cuda_runtime.h>

// Problem constants
#define B_      16
#define NQ      2048
#define DMODEL  1024
#define HEADS_  16
#define DHEAD   64
#define LTXT    77
#define LIMG    256
#define LCTX    333
#define SCALE_  0.125f

// Scratch (device globals: allocation-free per harness rules)
__device__ float g_q   [(size_t)B_ * NQ   * DMODEL];
__device__ float g_ktxt[(size_t)B_ * LTXT * DMODEL];
__device__ float g_vtxt[(size_t)B_ * LTXT * DMODEL];
__device__ float g_kimg[(size_t)B_ * LIMG * DMODEL];
__device__ float g_vimg[(size_t)B_ * LIMG * DMODEL];
__device__ float g_attn[(size_t)B_ * NQ   * DMODEL];

// ---------------------------------------------------------------------------
// Generic SGEMM: C[M x 1024] = mapped_rows(A) @ Bw[1024 x 1024] (+ bias)
// Row mapping handles batched slices of context:
//   src_row = (gr / rowsPerBatch) * batchRowStride + rowOffset + gr % rowsPerBatch
// 128x128 tile, BK=16, 256 threads, 8x8 per-thread microtile.
// ---------------------------------------------------------------------------
__global__ __launch_bounds__(256) void sgemm_kernel(
    const float* __restrict__ A, const float* __restrict__ Bw,
    float* __restrict__ C, const float* __restrict__ bias,
    int M, int rowsPerBatch, int batchRowStride, int rowOffset)
{
    const int N = 1024, K = 1024;
    __shared__ float As[16][129];   // [k][m], padded to dodge bank conflicts
    __shared__ float Bs[16][128];   // [k][n]

    const int tid = threadIdx.x;
    const int tx = tid & 15;        // 0..15 -> 8 output cols each
    const int ty = tid >> 4;        // 0..15 -> 8 output rows each
    const int blockRow = blockIdx.y * 128;
    const int blockCol = blockIdx.x * 128;

    // A loader: thread loads rows {aRow, aRow+64}, 4 consecutive k's
    const int aRow = tid >> 2;        // 0..63
    const int aCol = (tid & 3) * 4;   // 0,4,8,12
    const float* aPtr[2];
    bool aValid[2];
#pragma unroll
    for (int i = 0; i < 2; i++) {
        int gr = blockRow + aRow + i * 64;
        aValid[i] = (gr < M);
        int grc = aValid[i] ? gr : 0;
        int bidx   = grc / rowsPerBatch;
        int within = grc % rowsPerBatch;
        long srow = (long)bidx * batchRowStride + rowOffset + within;
        aPtr[i] = A + srow * (long)K + aCol;
    }

    // B loader: thread loads rows {bRow, bRow+8}, 4 consecutive n's
    const int bRow = tid >> 5;        // 0..7
    const int bCol = (tid & 31) * 4;  // 0..124
    const float* bPtr = Bw + (long)bRow * N + blockCol + bCol;

    float acc[8][8];
#pragma unroll
    for (int i = 0; i < 8; i++)
#pragma unroll
        for (int j = 0; j < 8; j++) acc[i][j] = 0.0f;

    for (int kt = 0; kt < K; kt += 16) {
#pragma unroll
        for (int i = 0; i < 2; i++) {
            float4 v = aValid[i] ? *(const float4*)(aPtr[i] + kt)
                                 : make_float4(0.f, 0.f, 0.f, 0.f);
            int row = aRow + i * 64;
            As[aCol + 0][row] = v.x;
            As[aCol + 1][row] = v.y;
            As[aCol + 2][row] = v.z;
            As[aCol + 3][row] = v.w;
        }
#pragma unroll
        for (int i = 0; i < 2; i++) {
            float4 v = *(const float4*)(bPtr + (long)(kt + i * 8) * N);
            *(float4*)&Bs[bRow + i * 8][bCol] = v;
        }
        __syncthreads();

#pragma unroll
        for (int kk = 0; kk < 16; kk++) {
            float ra[8], rb[8];
#pragma unroll
            for (int i = 0; i < 8; i++) ra[i] = As[kk][ty * 8 + i];
#pragma unroll
            for (int j = 0; j < 8; j++) rb[j] = Bs[kk][tx * 8 + j];
#pragma unroll
            for (int i = 0; i < 8; i++)
#pragma unroll
                for (int j = 0; j < 8; j++) acc[i][j] += ra[i] * rb[j];
        }
        __syncthreads();
    }

#pragma unroll
    for (int i = 0; i < 8; i++) {
        int gr = blockRow + ty * 8 + i;
        if (gr >= M) continue;
        float* cp = C + (long)gr * N + blockCol + tx * 8;
#pragma unroll
        for (int j = 0; j < 8; j++) {
            float v = acc[i][j];
            if (bias) v += bias[blockCol + tx * 8 + j];
            cp[j] = v;
        }
    }
}

// ---------------------------------------------------------------------------
// Dual flash attention: per block = (batch b, head h, 64 query rows).
// Pass 0: 77 text keys (2 chunks, masked); Pass 1: 256 image keys (4 chunks).
// out = softmax(QK_txt)V_txt + softmax(QK_img)V_img
// Thread owns a 4x4 tile of S and of O (rows rr..rr+3, cols cb..cb+3).
// ---------------------------------------------------------------------------
__global__ __launch_bounds__(256) void attn_kernel(
    const float* __restrict__ q,
    const float* __restrict__ ktxt, const float* __restrict__ vtxt,
    const float* __restrict__ kimg, const float* __restrict__ vimg,
    float* __restrict__ out)
{
    extern __shared__ float sm[];
    float* Qs = sm;                 // 64 x 65
    float* Ks = sm + 64 * 65;       // 64 x 65
    float* Vs = sm + 2 * 64 * 65;   // 64 x 65
    float* Ss = sm + 3 * 64 * 65;   // 64 x 65

    const int tid = threadIdx.x;
    const int b = blockIdx.y >> 4;
    const int h = blockIdx.y & 15;
    const int q0 = blockIdx.x * 64;
    const int rr = (tid >> 4) * 4;   // row base of 4x4 tile
    const int cb = (tid & 15) * 4;   // col base (key cols for S, dim cols for O)

    // Load Q tile (64 x 64)
    for (int i = tid; i < 64 * 16; i += 256) {
        int row = i >> 4;
        int c4  = (i & 15) * 4;
        float4 v = *(const float4*)(q + ((size_t)(b * NQ + q0 + row) * DMODEL) + h * DHEAD + c4);
        float* dst = Qs + row * 65 + c4;
        dst[0] = v.x; dst[1] = v.y; dst[2] = v.z; dst[3] = v.w;
    }

    float res[16];
#pragma unroll
    for (int i = 0; i < 16; i++) res[i] = 0.0f;

    for (int pass = 0; pass < 2; pass++) {
        const float* kb = pass ? kimg : ktxt;
        const float* vb = pass ? vimg : vtxt;
        const int L  = pass ? LIMG : LTXT;
        const int nCh = (L + 63) / 64;

        float m[4], l[4], o[16];
#pragma unroll
        for (int i = 0; i < 4; i++) { m[i] = -1e30f; l[i] = 0.0f; }
#pragma unroll
        for (int i = 0; i < 16; i++) o[i] = 0.0f;

        for (int ch = 0; ch < nCh; ch++) {
            const int j0 = ch * 64;
            __syncthreads();   // previous chunk's smem reads done (also covers Qs on first iter)

            // Load K,V chunk (zero-fill out-of-range keys)
            for (int i = tid; i < 64 * 16; i += 256) {
                int row = i >> 4;
                int c4  = (i & 15) * 4;
                int j = j0 + row;
                float4 kv = make_float4(0.f, 0.f, 0.f, 0.f);
                float4 vv = make_float4(0.f, 0.f, 0.f, 0.f);
                if (j < L) {
                    size_t base = ((size_t)(b * L + j) * DMODEL) + h * DHEAD + c4;
                    kv = *(const float4*)(kb + base);
                    vv = *(const float4*)(vb + base);
                }
                float* kd = Ks + row * 65 + c4;
                kd[0] = kv.x; kd[1] = kv.y; kd[2] = kv.z; kd[3] = kv.w;
                float* vd = Vs + row * 65 + c4;
                vd[0] = vv.x; vd[1] = vv.y; vd[2] = vv.z; vd[3] = vv.w;
            }
            __syncthreads();

            // S = Q K^T for this thread's 4x4 tile
            float s[16];
#pragma unroll
            for (int i = 0; i < 16; i++) s[i] = 0.0f;
            for (int k = 0; k < 64; k++) {
                float qv[4], kv[4];
#pragma unroll
                for (int i = 0; i < 4; i++) qv[i] = Qs[(rr + i) * 65 + k];
#pragma unroll
                for (int i = 0; i < 4; i++) kv[i] = Ks[(cb + i) * 65 + k];
#pragma unroll
                for (int i = 0; i < 4; i++)
#pragma unroll
                    for (int j = 0; j < 4; j++) s[i * 4 + j] += qv[i] * kv[j];
            }
            // Publish masked, scaled scores
#pragma unroll
            for (int i = 0; i < 4; i++)
#pragma unroll
                for (int j = 0; j < 4; j++) {
                    int gj = j0 + cb + j;
                    Ss[(rr + i) * 65 + cb + j] =
                        (gj < L) ? s[i * 4 + j] * SCALE_ : -1e30f;
                }
            __syncthreads();

            // Online softmax stats (each thread redundantly scans its 4 rows)
            float mnew[4];
#pragma unroll
            for (int i = 0; i < 4; i++) {
                const float* srow = Ss + (rr + i) * 65;
                float mc = -1e30f;
                for (int j = 0; j < 64; j++) mc = fmaxf(mc, srow[j]);
                float mn = fmaxf(m[i], mc);
                float corr = __expf(m[i] - mn);
                m[i] = mn; mnew[i] = mn;
                l[i] *= corr;
#pragma unroll
                for (int j = 0; j < 4; j++) o[i * 4 + j] *= corr;
            }
            __syncthreads();   // all max-scans done before overwriting Ss with p

            // p = exp(S - m); write owned entries (masked -> 0)
#pragma unroll
            for (int i = 0; i < 4; i++)
#pragma unroll
                for (int j = 0; j < 4; j++) {
                    int gj = j0 + cb + j;
                    float p = (gj < L) ? __expf(s[i * 4 + j] * SCALE_ - mnew[i]) : 0.0f;
                    Ss[(rr + i) * 65 + cb + j] = p;
                }
            __syncthreads();

            // l += row sums;  O += P V
#pragma unroll
            for (int i = 0; i < 4; i++) {
                const float* prow = Ss + (rr + i) * 65;
                float sum = 0.0f;
                for (int j = 0; j < 64; j++) sum += prow[j];
                l[i] += sum;
            }
            for (int jk = 0; jk < 64; jk++) {
                float pv[4], vv[4];
#pragma unroll
                for (int i = 0; i < 4; i++) pv[i] = Ss[(rr + i) * 65 + jk];
#pragma unroll
                for (int j = 0; j < 4; j++) vv[j] = Vs[jk * 65 + cb + j];
#pragma unroll
                for (int i = 0; i < 4; i++)
#pragma unroll
                    for (int j = 0; j < 4; j++) o[i * 4 + j] += pv[i] * vv[j];
            }
        }

        // Finalize pass: res += O / l   (IMG_SCALE = 1)
#pragma unroll
        for (int i = 0; i < 4; i++) {
            float inv = 1.0f / l[i];
#pragma unroll
            for (int j = 0; j < 4; j++) res[i * 4 + j] += o[i * 4 + j] * inv;
        }
    }

    // Write result tile
#pragma unroll
    for (int i = 0; i < 4; i++) {
        float* op = out + ((size_t)(b * NQ + q0 + rr + i) * DMODEL) + h * DHEAD + cb;
#pragma unroll
        for (int j = 0; j < 4; j++) op[j] = res[i * 4 + j];
    }
}

// ---------------------------------------------------------------------------
// Launch
// ---------------------------------------------------------------------------
extern "C" void kernel_launch(void* const* d_in, const int* in_sizes, int n_in,
                              void* d_out, int out_size)
{
    const float* x    = (const float*)d_in[0];
    const float* ctx  = (const float*)d_in[1];
    const float* Wq   = (const float*)d_in[2];
    const float* Wk   = (const float*)d_in[3];
    const float* Wv   = (const float*)d_in[4];
    const float* Wkip = (const float*)d_in[5];
    const float* Wvip = (const float*)d_in[6];
    const float* Wo   = (const float*)d_in[7];
    const float* bo   = (const float*)d_in[8];
    float* out = (float*)d_out;

    float *q, *kt, *vt, *ki, *vi, *ao;
    cudaGetSymbolAddress((void**)&q,  g_q);
    cudaGetSymbolAddress((void**)&kt, g_ktxt);
    cudaGetSymbolAddress((void**)&vt, g_vtxt);
    cudaGetSymbolAddress((void**)&ki, g_kimg);
    cudaGetSymbolAddress((void**)&vi, g_vimg);
    cudaGetSymbolAddress((void**)&ao, g_attn);

    const dim3 thr(256);
    const int MQ   = B_ * NQ;     // 32768
    const int MTXT = B_ * LTXT;   // 1232
    const int MIMG = B_ * LIMG;   // 4096

    // Projections
    sgemm_kernel<<<dim3(8, (MQ   + 127) / 128), thr>>>(x,   Wq,   q,  nullptr, MQ,   NQ,   NQ,   0);
    sgemm_kernel<<<dim3(8, (MTXT + 127) / 128), thr>>>(ctx, Wk,   kt, nullptr, MTXT, LTXT, LCTX, 0);
    sgemm_kernel<<<dim3(8, (MTXT + 127) / 128), thr>>>(ctx, Wv,   vt, nullptr, MTXT, LTXT, LCTX, 0);
    sgemm_kernel<<<dim3(8, (MIMG + 127) / 128), thr>>>(ctx, Wkip, ki, nullptr, MIMG, LIMG, LCTX, LTXT);
    sgemm_kernel<<<dim3(8, (MIMG + 127) / 128), thr>>>(ctx, Wvip, vi, nullptr, MIMG, LIMG, LCTX, LTXT);

    // Dual attention
    const int attnSmem = 4 * 64 * 65 * (int)sizeof(float);   // 66560 B
    cudaFuncSetAttribute(attn_kernel, cudaFuncAttributeMaxDynamicSharedMemorySize, attnSmem);
    attn_kernel<<<dim3(NQ / 64, B_ * HEADS_), thr, attnSmem>>>(q, kt, vt, ki, vi, ao);

    // Output projection + bias
    sgemm_kernel<<<dim3(8, (MQ + 127) / 128), thr>>>(ao, Wo, out, bo, MQ, NQ, NQ, 0);
}

// round 4
// speedup vs baseline: 1.5833x; 1.5833x over previous
#include <cuda_runtime.h>

// Problem constants
#define B_      16
#define NQ      2048
#define DMODEL  1024
#define HEADS_  16
#define DHEAD   64
#define LTXT    77
#define LIMG    256
#define LCTX    333
#define SCALE_  0.125f

#define NROWS_CTX (B_ * LCTX)     // 5328
#define MQ_   (B_ * NQ)           // 32768
#define MTXT_ (B_ * LTXT)         // 1232
#define MIMG_ (B_ * LIMG)         // 4096

// fp32 intermediates (attention consumes fp32)
__device__ float g_q   [(size_t)MQ_   * DMODEL];
__device__ float g_ktxt[(size_t)MTXT_ * DMODEL];
__device__ float g_vtxt[(size_t)MTXT_ * DMODEL];
__device__ float g_kimg[(size_t)MIMG_ * DMODEL];
__device__ float g_vimg[(size_t)MIMG_ * DMODEL];
__device__ float g_attn[(size_t)MQ_   * DMODEL];

// bf16 hi/lo packed-pair arrays (1 uint = 2 bf16, low half = even k)
__device__ unsigned g_xhi [(size_t)MQ_ * 512];
__device__ unsigned g_xlo [(size_t)MQ_ * 512];
__device__ unsigned g_chi [(size_t)NROWS_CTX * 512];
__device__ unsigned g_clo [(size_t)NROWS_CTX * 512];
__device__ unsigned g_aohi[(size_t)MQ_ * 512];
__device__ unsigned g_aolo[(size_t)MQ_ * 512];
__device__ unsigned g_whi [6ull * DMODEL * 512];
__device__ unsigned g_wlo [6ull * DMODEL * 512];

// ---------------------------------------------------------------------------
// helpers
// ---------------------------------------------------------------------------
__device__ __forceinline__ unsigned smem_u32(const void* p) {
    unsigned a;
    asm("{ .reg .u64 t; cvta.to.shared.u64 t, %1; cvt.u32.u64 %0, t; }"
        : "=r"(a) : "l"(p));
    return a;
}

// Split float2 into packed bf16 hi-pair and lo-pair. low 16 bits = v.x.
__device__ __forceinline__ void split_bf16(float2 v, unsigned& hi, unsigned& lo) {
    unsigned h;
    asm("cvt.rn.bf16x2.f32 %0, %1, %2;" : "=r"(h) : "f"(v.y), "f"(v.x));
    float hx = __uint_as_float((h & 0xFFFFu) << 16);
    float hy = __uint_as_float(h & 0xFFFF0000u);
    float lx = v.x - hx;
    float ly = v.y - hy;
    unsigned l;
    asm("cvt.rn.bf16x2.f32 %0, %1, %2;" : "=r"(l) : "f"(ly), "f"(lx));
    hi = h; lo = l;
}

#define MMA16816(d, a, b) \
    asm volatile("mma.sync.aligned.m16n8k16.row.col.f32.bf16.bf16.f32 " \
        "{%0,%1,%2,%3}, {%4,%5,%6,%7}, {%8,%9}, {%0,%1,%2,%3};" \
        : "+f"((d)[0]), "+f"((d)[1]), "+f"((d)[2]), "+f"((d)[3]) \
        : "r"((a)[0]), "r"((a)[1]), "r"((a)[2]), "r"((a)[3]), \
          "r"((b)[0]), "r"((b)[1]))

#define CP_ASYNC16(dst, src, srcsz) \
    asm volatile("cp.async.ca.shared.global [%0], [%1], 16, %2;" \
                 :: "r"(dst), "l"(src), "r"(srcsz))
#define CP_COMMIT()  asm volatile("cp.async.commit_group;" ::: "memory")
#define CP_WAIT1()   asm volatile("cp.async.wait_group 1;" ::: "memory")

// ---------------------------------------------------------------------------
// Weight transpose + split: W[k][n] (1024x1024) -> Whi/Wlo [n][512] packed pairs
// ---------------------------------------------------------------------------
__global__ __launch_bounds__(256) void wsplit_kernel(
    const float* __restrict__ W, unsigned* __restrict__ Whi, unsigned* __restrict__ Wlo)
{
    __shared__ float t[32][33];
    const int bx = blockIdx.x * 32;   // n
    const int by = blockIdx.y * 32;   // k
    const int tx = threadIdx.x, ty = threadIdx.y;
#pragma unroll
    for (int r = 0; r < 4; r++)
        t[ty * 4 + r][tx] = W[(size_t)(by + ty * 4 + r) * DMODEL + bx + tx];
    __syncthreads();
#pragma unroll
    for (int r = 0; r < 2; r++) {
        int kp = ty * 2 + r;
        float2 v = make_float2(t[2 * kp][tx], t[2 * kp + 1][tx]);
        unsigned hi, lo;
        split_bf16(v, hi, lo);
        size_t idx = (size_t)(bx + tx) * 512 + (by >> 1) + kp;
        Whi[idx] = hi;
        Wlo[idx] = lo;
    }
}

// ---------------------------------------------------------------------------
// Activation split: fp32 array -> hi/lo packed pairs (grid-stride over pairs)
// ---------------------------------------------------------------------------
__global__ __launch_bounds__(256) void asplit_kernel(
    const float* __restrict__ in, unsigned* __restrict__ hi, unsigned* __restrict__ lo,
    long npairs)
{
    long i = (long)blockIdx.x * blockDim.x + threadIdx.x;
    const long stride = (long)gridDim.x * blockDim.x;
    for (; i < npairs; i += stride) {
        float2 v = ((const float2*)in)[i];
        unsigned h, l;
        split_bf16(v, h, l);
        hi[i] = h; lo[i] = l;
    }
}

// ---------------------------------------------------------------------------
// bf16x3 compensated GEMM via mma.sync:
//   C[M x 1024] = mapped_rows(A) @ Wt^T (+bias)
// A given as hi/lo packed-pair arrays, row stride 512 u32.
// Wt hi/lo: [n][512].
// CTA tile 128(M) x 256(N), BK=32 (16 pairs), 8 warps of 64x64.
// Double-buffered cp.async pipeline.
// ---------------------------------------------------------------------------
#define GBM 128
#define GBN 256
#define NCHUNK 32
// smem per buffer (u32 words): Ahi 128*20, Alo 128*20, Bhi 256*20, Blo 256*20
#define W_AH 0
#define W_AL 2560
#define W_BH 5120
#define W_BL 10240
#define W_BUF 15360
#define GEMM_SMEM_BYTES (2 * W_BUF * 4)   // 122880

__global__ __launch_bounds__(256) void gemm_bf16x3_kernel(
    const unsigned* __restrict__ Ahi, const unsigned* __restrict__ Alo,
    const unsigned* __restrict__ Bhi, const unsigned* __restrict__ Blo,
    float* __restrict__ C, const float* __restrict__ bias,
    int M, int rowsPerBatch, int batchRowStride, int rowOffset)
{
    extern __shared__ unsigned su[];
    const unsigned smb = smem_u32(su);

    const int tid  = threadIdx.x;
    const int wid  = tid >> 5;
    const int lane = tid & 31;
    const int m0 = blockIdx.y * GBM;
    const int n0 = blockIdx.x * GBN;
    const int warpM = (wid & 1) * 64;
    const int warpN = (wid >> 1) * 64;

    // Loader assignments: A 2 segs, B 4 segs per thread (16B each, x hi/lo)
    int  aRow[2], aC[2];
    long aSrc[2];
    unsigned aZ[2];
#pragma unroll
    for (int t = 0; t < 2; t++) {
        int seg = tid + t * 256;          // 0..511
        aRow[t] = seg >> 2;
        aC[t]   = seg & 3;
        int gr = m0 + aRow[t];
        bool ok = (gr < M);
        int grc = ok ? gr : 0;
        int bidx = grc / rowsPerBatch;
        int within = grc % rowsPerBatch;
        long srow = (long)bidx * batchRowStride + rowOffset + within;
        aSrc[t] = srow * 512 + aC[t] * 4;
        aZ[t] = ok ? 16u : 0u;
    }
    int bRow[4], bC[4];
    long bSrc[4];
#pragma unroll
    for (int t = 0; t < 4; t++) {
        int seg = tid + t * 256;          // 0..1023
        bRow[t] = seg >> 2;
        bC[t]   = seg & 3;
        bSrc[t] = (long)(n0 + bRow[t]) * 512 + bC[t] * 4;
    }

    float acc[4][8][4];
#pragma unroll
    for (int mt = 0; mt < 4; mt++)
#pragma unroll
        for (int nt = 0; nt < 8; nt++)
#pragma unroll
            for (int r = 0; r < 4; r++) acc[mt][nt][r] = 0.0f;

    // issue loads for a chunk into buffer buf
    auto issue = [&](int chunk, int buf) {
        const int kw = chunk * 16;
        const unsigned base = smb + (unsigned)buf * (W_BUF * 4);
#pragma unroll
        for (int t = 0; t < 2; t++) {
            unsigned doff = (unsigned)(aRow[t] * 20 + aC[t] * 4) * 4;
            CP_ASYNC16(base + W_AH * 4 + doff, Ahi + aSrc[t] + kw, aZ[t]);
            CP_ASYNC16(base + W_AL * 4 + doff, Alo + aSrc[t] + kw, aZ[t]);
        }
#pragma unroll
        for (int t = 0; t < 4; t++) {
            unsigned doff = (unsigned)(bRow[t] * 20 + bC[t] * 4) * 4;
            CP_ASYNC16(base + W_BH * 4 + doff, Bhi + bSrc[t] + kw, 16u);
            CP_ASYNC16(base + W_BL * 4 + doff, Blo + bSrc[t] + kw, 16u);
        }
    };

    issue(0, 0);
    CP_COMMIT();

    for (int c = 0; c < NCHUNK; c++) {
        if (c + 1 < NCHUNK) issue(c + 1, (c + 1) & 1);
        CP_COMMIT();
        CP_WAIT1();
        __syncthreads();

        const unsigned* sAh = su + (c & 1) * W_BUF + W_AH;
        const unsigned* sAl = su + (c & 1) * W_BUF + W_AL;
        const unsigned* sBh = su + (c & 1) * W_BUF + W_BH;
        const unsigned* sBl = su + (c & 1) * W_BUF + W_BL;

#pragma unroll
        for (int ks = 0; ks < 2; ks++) {
            const int kp0 = ks * 8 + (lane & 3);
            const int r0  = warpM + (lane >> 2);
            unsigned ah[4][4], al[4][4];
#pragma unroll
            for (int mt = 0; mt < 4; mt++) {
                int rw = (r0 + mt * 16) * 20;
                ah[mt][0] = sAh[rw + kp0];
                ah[mt][1] = sAh[rw + 160 + kp0];
                ah[mt][2] = sAh[rw + kp0 + 4];
                ah[mt][3] = sAh[rw + 160 + kp0 + 4];
                al[mt][0] = sAl[rw + kp0];
                al[mt][1] = sAl[rw + 160 + kp0];
                al[mt][2] = sAl[rw + kp0 + 4];
                al[mt][3] = sAl[rw + 160 + kp0 + 4];
            }
            const int nbase = warpN + (lane >> 2);
#pragma unroll
            for (int nt = 0; nt < 8; nt++) {
                int nw = (nbase + nt * 8) * 20;
                unsigned bh[2], bl[2];
                bh[0] = sBh[nw + kp0];
                bh[1] = sBh[nw + kp0 + 4];
                bl[0] = sBl[nw + kp0];
                bl[1] = sBl[nw + kp0 + 4];
#pragma unroll
                for (int mt = 0; mt < 4; mt++) {
                    MMA16816(acc[mt][nt], ah[mt], bh);
                    MMA16816(acc[mt][nt], ah[mt], bl);
                    MMA16816(acc[mt][nt], al[mt], bh);
                }
            }
        }
        __syncthreads();
    }

    // Epilogue: fp32 stores (+bias)
#pragma unroll
    for (int mt = 0; mt < 4; mt++) {
        int gr0 = m0 + warpM + mt * 16 + (lane >> 2);
#pragma unroll
        for (int nt = 0; nt < 8; nt++) {
            int gc = n0 + warpN + nt * 8 + 2 * (lane & 3);
            float b0 = 0.f, b1 = 0.f;
            if (bias) { b0 = bias[gc]; b1 = bias[gc + 1]; }
            if (gr0 < M) {
                float2 v = make_float2(acc[mt][nt][0] + b0, acc[mt][nt][1] + b1);
                *(float2*)(C + (size_t)gr0 * DMODEL + gc) = v;
            }
            if (gr0 + 8 < M) {
                float2 v = make_float2(acc[mt][nt][2] + b0, acc[mt][nt][3] + b1);
                *(float2*)(C + (size_t)(gr0 + 8) * DMODEL + gc) = v;
            }
        }
    }
}

// ---------------------------------------------------------------------------
// Dual flash attention (unchanged from R1 — fp32, correct at 1.2e-6)
// ---------------------------------------------------------------------------
__global__ __launch_bounds__(256) void attn_kernel(
    const float* __restrict__ q,
    const float* __restrict__ ktxt, const float* __restrict__ vtxt,
    const float* __restrict__ kimg, const float* __restrict__ vimg,
    float* __restrict__ out)
{
    extern __shared__ float smf[];
    float* Qs = smf;
    float* Ks = smf + 64 * 65;
    float* Vs = smf + 2 * 64 * 65;
    float* Ss = smf + 3 * 64 * 65;

    const int tid = threadIdx.x;
    const int b = blockIdx.y >> 4;
    const int h = blockIdx.y & 15;
    const int q0 = blockIdx.x * 64;
    const int rr = (tid >> 4) * 4;
    const int cb = (tid & 15) * 4;

    for (int i = tid; i < 64 * 16; i += 256) {
        int row = i >> 4;
        int c4  = (i & 15) * 4;
        float4 v = *(const float4*)(q + ((size_t)(b * NQ + q0 + row) * DMODEL) + h * DHEAD + c4);
        float* dst = Qs + row * 65 + c4;
        dst[0] = v.x; dst[1] = v.y; dst[2] = v.z; dst[3] = v.w;
    }

    float res[16];
#pragma unroll
    for (int i = 0; i < 16; i++) res[i] = 0.0f;

    for (int pass = 0; pass < 2; pass++) {
        const float* kb = pass ? kimg : ktxt;
        const float* vb = pass ? vimg : vtxt;
        const int L  = pass ? LIMG : LTXT;
        const int nCh = (L + 63) / 64;

        float m[4], l[4], o[16];
#pragma unroll
        for (int i = 0; i < 4; i++) { m[i] = -1e30f; l[i] = 0.0f; }
#pragma unroll
        for (int i = 0; i < 16; i++) o[i] = 0.0f;

        for (int ch = 0; ch < nCh; ch++) {
            const int j0 = ch * 64;
            __syncthreads();

            for (int i = tid; i < 64 * 16; i += 256) {
                int row = i >> 4;
                int c4  = (i & 15) * 4;
                int j = j0 + row;
                float4 kv = make_float4(0.f, 0.f, 0.f, 0.f);
                float4 vv = make_float4(0.f, 0.f, 0.f, 0.f);
                if (j < L) {
                    size_t base = ((size_t)(b * L + j) * DMODEL) + h * DHEAD + c4;
                    kv = *(const float4*)(kb + base);
                    vv = *(const float4*)(vb + base);
                }
                float* kd = Ks + row * 65 + c4;
                kd[0] = kv.x; kd[1] = kv.y; kd[2] = kv.z; kd[3] = kv.w;
                float* vd = Vs + row * 65 + c4;
                vd[0] = vv.x; vd[1] = vv.y; vd[2] = vv.z; vd[3] = vv.w;
            }
            __syncthreads();

            float s[16];
#pragma unroll
            for (int i = 0; i < 16; i++) s[i] = 0.0f;
            for (int k = 0; k < 64; k++) {
                float qv[4], kv[4];
#pragma unroll
                for (int i = 0; i < 4; i++) qv[i] = Qs[(rr + i) * 65 + k];
#pragma unroll
                for (int i = 0; i < 4; i++) kv[i] = Ks[(cb + i) * 65 + k];
#pragma unroll
                for (int i = 0; i < 4; i++)
#pragma unroll
                    for (int j = 0; j < 4; j++) s[i * 4 + j] += qv[i] * kv[j];
            }
#pragma unroll
            for (int i = 0; i < 4; i++)
#pragma unroll
                for (int j = 0; j < 4; j++) {
                    int gj = j0 + cb + j;
                    Ss[(rr + i) * 65 + cb + j] =
                        (gj < L) ? s[i * 4 + j] * SCALE_ : -1e30f;
                }
            __syncthreads();

            float mnew[4];
#pragma unroll
            for (int i = 0; i < 4; i++) {
                const float* srow = Ss + (rr + i) * 65;
                float mc = -1e30f;
                for (int j = 0; j < 64; j++) mc = fmaxf(mc, srow[j]);
                float mn = fmaxf(m[i], mc);
                float corr = __expf(m[i] - mn);
                m[i] = mn; mnew[i] = mn;
                l[i] *= corr;
#pragma unroll
                for (int j = 0; j < 4; j++) o[i * 4 + j] *= corr;
            }
            __syncthreads();

#pragma unroll
            for (int i = 0; i < 4; i++)
#pragma unroll
                for (int j = 0; j < 4; j++) {
                    int gj = j0 + cb + j;
                    float p = (gj < L) ? __expf(s[i * 4 + j] * SCALE_ - mnew[i]) : 0.0f;
                    Ss[(rr + i) * 65 + cb + j] = p;
                }
            __syncthreads();

#pragma unroll
            for (int i = 0; i < 4; i++) {
                const float* prow = Ss + (rr + i) * 65;
                float sum = 0.0f;
                for (int j = 0; j < 64; j++) sum += prow[j];
                l[i] += sum;
            }
            for (int jk = 0; jk < 64; jk++) {
                float pv[4], vv[4];
#pragma unroll
                for (int i = 0; i < 4; i++) pv[i] = Ss[(rr + i) * 65 + jk];
#pragma unroll
                for (int j = 0; j < 4; j++) vv[j] = Vs[jk * 65 + cb + j];
#pragma unroll
                for (int i = 0; i < 4; i++)
#pragma unroll
                    for (int j = 0; j < 4; j++) o[i * 4 + j] += pv[i] * vv[j];
            }
        }

#pragma unroll
        for (int i = 0; i < 4; i++) {
            float inv = 1.0f / l[i];
#pragma unroll
            for (int j = 0; j < 4; j++) res[i * 4 + j] += o[i * 4 + j] * inv;
        }
    }

#pragma unroll
    for (int i = 0; i < 4; i++) {
        float* op = out + ((size_t)(b * NQ + q0 + rr + i) * DMODEL) + h * DHEAD + cb;
#pragma unroll
        for (int j = 0; j < 4; j++) op[j] = res[i * 4 + j];
    }
}

// ---------------------------------------------------------------------------
// Launch
// ---------------------------------------------------------------------------
extern "C" void kernel_launch(void* const* d_in, const int* in_sizes, int n_in,
                              void* d_out, int out_size)
{
    const float* x    = (const float*)d_in[0];
    const float* ctx  = (const float*)d_in[1];
    const float* Wq   = (const float*)d_in[2];
    const float* Wk   = (const float*)d_in[3];
    const float* Wv   = (const float*)d_in[4];
    const float* Wkip = (const float*)d_in[5];
    const float* Wvip = (const float*)d_in[6];
    const float* Wo   = (const float*)d_in[7];
    const float* bo   = (const float*)d_in[8];
    float* out = (float*)d_out;

    float *q, *kt, *vt, *ki, *vi, *ao;
    unsigned *xhi, *xlo, *chi, *clo, *aohi, *aolo, *whi, *wlo;
    cudaGetSymbolAddress((void**)&q,   g_q);
    cudaGetSymbolAddress((void**)&kt,  g_ktxt);
    cudaGetSymbolAddress((void**)&vt,  g_vtxt);
    cudaGetSymbolAddress((void**)&ki,  g_kimg);
    cudaGetSymbolAddress((void**)&vi,  g_vimg);
    cudaGetSymbolAddress((void**)&ao,  g_attn);
    cudaGetSymbolAddress((void**)&xhi, g_xhi);
    cudaGetSymbolAddress((void**)&xlo, g_xlo);
    cudaGetSymbolAddress((void**)&chi, g_chi);
    cudaGetSymbolAddress((void**)&clo, g_clo);
    cudaGetSymbolAddress((void**)&aohi, g_aohi);
    cudaGetSymbolAddress((void**)&aolo, g_aolo);
    cudaGetSymbolAddress((void**)&whi, g_whi);
    cudaGetSymbolAddress((void**)&wlo, g_wlo);

    const size_t WSZ = (size_t)DMODEL * 512;
    const float* Ws[6] = {Wq, Wk, Wv, Wkip, Wvip, Wo};

    // Weight transpose+split (6 x ~10us)
    const dim3 wthr(32, 8), wgrd(32, 32);
    for (int i = 0; i < 6; i++)
        wsplit_kernel<<<wgrd, wthr>>>(Ws[i], whi + i * WSZ, wlo + i * WSZ);

    // Activation splits
    asplit_kernel<<<2048, 256>>>(x,   xhi, xlo, (long)MQ_ * 512);
    asplit_kernel<<<1024, 256>>>(ctx, chi, clo, (long)NROWS_CTX * 512);

    cudaFuncSetAttribute(gemm_bf16x3_kernel,
                         cudaFuncAttributeMaxDynamicSharedMemorySize, GEMM_SMEM_BYTES);

    // Projections (grid: 4 n-blocks x m-blocks)
    gemm_bf16x3_kernel<<<dim3(4, (MQ_ + 127) / 128), 256, GEMM_SMEM_BYTES>>>(
        xhi, xlo, whi + 0 * WSZ, wlo + 0 * WSZ, q,  nullptr, MQ_,   MQ_,  MQ_,  0);
    gemm_bf16x3_kernel<<<dim3(4, (MTXT_ + 127) / 128), 256, GEMM_SMEM_BYTES>>>(
        chi, clo, whi + 1 * WSZ, wlo + 1 * WSZ, kt, nullptr, MTXT_, LTXT, LCTX, 0);
    gemm_bf16x3_kernel<<<dim3(4, (MTXT_ + 127) / 128), 256, GEMM_SMEM_BYTES>>>(
        chi, clo, whi + 2 * WSZ, wlo + 2 * WSZ, vt, nullptr, MTXT_, LTXT, LCTX, 0);
    gemm_bf16x3_kernel<<<dim3(4, (MIMG_ + 127) / 128), 256, GEMM_SMEM_BYTES>>>(
        chi, clo, whi + 3 * WSZ, wlo + 3 * WSZ, ki, nullptr, MIMG_, LIMG, LCTX, LTXT);
    gemm_bf16x3_kernel<<<dim3(4, (MIMG_ + 127) / 128), 256, GEMM_SMEM_BYTES>>>(
        chi, clo, whi + 4 * WSZ, wlo + 4 * WSZ, vi, nullptr, MIMG_, LIMG, LCTX, LTXT);

    // Attention
    const int attnSmem = 4 * 64 * 65 * (int)sizeof(float);
    cudaFuncSetAttribute(attn_kernel, cudaFuncAttributeMaxDynamicSharedMemorySize, attnSmem);
    attn_kernel<<<dim3(NQ / 64, B_ * HEADS_), 256, attnSmem>>>(q, kt, vt, ki, vi, ao);

    // Split attention output, then O-projection (+bias)
    asplit_kernel<<<2048, 256>>>(ao, aohi, aolo, (long)MQ_ * 512);
    gemm_bf16x3_kernel<<<dim3(4, (MQ_ + 127) / 128), 256, GEMM_SMEM_BYTES>>>(
        aohi, aolo, whi + 5 * WSZ, wlo + 5 * WSZ, out, bo, MQ_, MQ_, MQ_, 0);
}